// round 9
// baseline (speedup 1.0000x reference)
#include <cuda_runtime.h>
#include <cuda_fp16.h>
#include <cstdint>
#include <cstddef>

// ============================================================
// Problem constants
// ============================================================
#define TOKENS 4096
#define DIN    4096
#define DOUT   4096
#define NWELEM (16777216)          // 4096*4096
// quantile(0.9) over n=16777216: index 0.9*(n-1)=15099493.5 -> ranks:
#define RANK0  15099493ULL
#define RANK1  15099494ULL

#define PANEL_BYTES ((size_t)TOKENS * 128)   // bytes per K-panel (both x and w): 512KB

// ============================================================
// Device scratch (static __device__ arrays: the sanctioned scratch)
// g_xh / g_wh hold fp16 data in PANEL layout, SW128 pre-swizzled:
//   element (row, k) lives at panel(k/64)*PANEL_BYTES + SW128(row*128 + (k%64)*2)
// ============================================================
__device__ __align__(1024) __half g_xh[(size_t)TOKENS * DIN];   // x in fp16, panelized
__device__ __align__(1024) __half g_wh[(size_t)DOUT * DIN];     // masked W fp16, panelized
__device__ unsigned int  g_hist1[4096];                // top-12-bit histogram
__device__ unsigned int  g_hist2[2][1 << 20];          // low-20-bit histograms (2 ranks)
__device__ unsigned int  g_chunk[2][1024];             // 1024-bin chunk sums of g_hist2
__device__ unsigned int  g_hibin[2];
__device__ unsigned int  g_irank[2];
__device__ float         g_thr;

// ============================================================
// PTX helpers (baseline PTX only — compute_103-safe, no tcgen05)
// ============================================================
__device__ __forceinline__ uint32_t smem_u32(const void* p) {
    uint32_t a;
    asm("{ .reg .u64 t; cvta.to.shared.u64 t, %1; cvt.u32.u64 %0, t; }" : "=r"(a) : "l"(p));
    return a;
}

__device__ __forceinline__ uint32_t elect_one() {
    uint32_t pred;
    asm volatile("{\n\t.reg .pred p;\n\telect.sync _|p, 0xFFFFFFFF;\n\tselp.b32 %0, 1, 0, p;\n\t}"
                 : "=r"(pred));
    return pred;
}

#define MBAR_INIT(addr, cnt) \
    asm volatile("mbarrier.init.shared.b64 [%0], %1;" :: "r"(addr), "r"(cnt) : "memory")
#define MBAR_ARRIVE(addr) \
    asm volatile("mbarrier.arrive.shared.b64 _, [%0];" :: "r"(addr) : "memory")
#define MBAR_EXPECT_TX(addr, bytes) \
    asm volatile("mbarrier.arrive.expect_tx.shared.b64 _, [%0], %1;" :: "r"(addr), "r"(bytes) : "memory")

__device__ __forceinline__ void mbar_wait_acq(uint32_t addr, uint32_t parity) {
    asm volatile(
        "{\n\t.reg .pred P;\n\t"
        "WLA_%=:\n\t"
        "mbarrier.try_wait.parity.acquire.cta.shared::cta.b64 P, [%0], %1, 0x989680;\n\t"
        "@P bra.uni WDA_%=;\n\t"
        "bra.uni WLA_%=;\n\t"
        "WDA_%=:\n\t}"
        :: "r"(addr), "r"(parity) : "memory");
}
__device__ __forceinline__ void mbar_wait_rlx(uint32_t addr, uint32_t parity) {
    asm volatile(
        "{\n\t.reg .pred P;\n\t"
        "WLR_%=:\n\t"
        "mbarrier.try_wait.parity.relaxed.cta.shared::cta.b64 P, [%0], %1, 0x989680;\n\t"
        "@P bra.uni WDR_%=;\n\t"
        "bra.uni WLR_%=;\n\t"
        "WDR_%=:\n\t}"
        :: "r"(addr), "r"(parity) : "memory");
}

// Non-tensor bulk copy: contiguous GMEM -> SMEM, tx-count completion (UBLKCP).
__device__ __forceinline__ void bulk_g2s(uint32_t dst, const void* src,
                                         uint32_t bytes, uint32_t mbar) {
    asm volatile(
        "cp.async.bulk.shared::cluster.global.mbarrier::complete_tx::bytes [%0], [%1], %2, [%3];"
        :: "r"(dst), "l"(src), "r"(bytes), "r"(mbar) : "memory");
}

#define SW128(off) ((off) ^ (((off) >> 3) & 0x70))

// ldmatrix 4x 8x8 b16 matrices (baseline sm_75+)
__device__ __forceinline__ void ldmx4(uint32_t& r0, uint32_t& r1, uint32_t& r2, uint32_t& r3,
                                      uint32_t addr) {
    asm volatile("ldmatrix.sync.aligned.m8n8.x4.shared.b16 {%0,%1,%2,%3}, [%4];"
                 : "=r"(r0), "=r"(r1), "=r"(r2), "=r"(r3) : "r"(addr));
}

// mma.sync m16n8k16 fp16 in / fp32 accum (baseline sm_80+)
__device__ __forceinline__ void mma16816(float* d, const uint32_t* a, const uint32_t* b) {
    asm volatile(
        "mma.sync.aligned.m16n8k16.row.col.f32.f16.f16.f32 "
        "{%0,%1,%2,%3}, {%4,%5,%6,%7}, {%8,%9}, {%0,%1,%2,%3};"
        : "+f"(d[0]), "+f"(d[1]), "+f"(d[2]), "+f"(d[3])
        : "r"(a[0]), "r"(a[1]), "r"(a[2]), "r"(a[3]), "r"(b[0]), "r"(b[1]));
}

// ============================================================
// Threshold: exact radix-select of order stats RANK0/RANK1 over |W| bits
// ============================================================
__global__ void hist1_kernel(const float4* __restrict__ w) {
    __shared__ unsigned int h[4096];
    for (int i = threadIdx.x; i < 4096; i += blockDim.x) h[i] = 0;
    __syncthreads();
    const int n4 = NWELEM / 4;
    int stride = gridDim.x * blockDim.x;
    for (int i = blockIdx.x * blockDim.x + threadIdx.x; i < n4; i += stride) {
        float4 v = w[i];
        atomicAdd(&h[__float_as_uint(fabsf(v.x)) >> 20], 1u);
        atomicAdd(&h[__float_as_uint(fabsf(v.y)) >> 20], 1u);
        atomicAdd(&h[__float_as_uint(fabsf(v.z)) >> 20], 1u);
        atomicAdd(&h[__float_as_uint(fabsf(v.w)) >> 20], 1u);
    }
    __syncthreads();
    for (int i = threadIdx.x; i < 4096; i += blockDim.x)
        if (h[i]) atomicAdd(&g_hist1[i], h[i]);
}

__global__ void select1_kernel() {
    __shared__ unsigned long long psum[1024];
    int tid = threadIdx.x;
    unsigned int c[4];
    unsigned long long s = 0;
    #pragma unroll
    for (int j = 0; j < 4; j++) { c[j] = g_hist1[tid * 4 + j]; s += c[j]; }
    psum[tid] = s;
    __syncthreads();
    for (int off = 1; off < 1024; off <<= 1) {
        unsigned long long v = 0;
        if (tid >= off) v = psum[tid - off];
        __syncthreads();
        psum[tid] += v;
        __syncthreads();
    }
    unsigned long long excl = tid ? psum[tid - 1] : 0ULL;
    const unsigned long long R[2] = {RANK0, RANK1};
    #pragma unroll
    for (int t = 0; t < 2; t++) {
        unsigned long long run = excl;
        #pragma unroll
        for (int j = 0; j < 4; j++) {
            if (R[t] >= run && R[t] < run + c[j]) {
                g_hibin[t] = tid * 4 + j;
                g_irank[t] = (unsigned int)(R[t] - run);
            }
            run += c[j];
        }
    }
}

__global__ void hist2_kernel(const float4* __restrict__ w) {
    unsigned int b0 = g_hibin[0], b1 = g_hibin[1];
    const int n4 = NWELEM / 4;
    int stride = gridDim.x * blockDim.x;
    for (int i = blockIdx.x * blockDim.x + threadIdx.x; i < n4; i += stride) {
        float4 v = w[i];
        float vv[4] = {v.x, v.y, v.z, v.w};
        #pragma unroll
        for (int j = 0; j < 4; j++) {
            unsigned int u = __float_as_uint(fabsf(vv[j]));
            unsigned int hi = u >> 20, lo = u & 0xFFFFFu;
            if (hi == b0) atomicAdd(&g_hist2[0][lo], 1u);
            if (hi == b1) atomicAdd(&g_hist2[1][lo], 1u);
        }
    }
}

// Full-grid reduction: 2^20 bins -> 1024 chunk sums per histogram.
__global__ void reduce2_kernel() {
    int t = blockIdx.y;
    int base = blockIdx.x * 1024 + threadIdx.x * 4;
    const uint4* p = reinterpret_cast<const uint4*>(&g_hist2[t][base]);
    uint4 v = *p;
    unsigned int s = v.x + v.y + v.z + v.w;
    __shared__ unsigned int red[256];
    red[threadIdx.x] = s;
    __syncthreads();
    for (int off = 128; off > 0; off >>= 1) {
        if (threadIdx.x < off) red[threadIdx.x] += red[threadIdx.x + off];
        __syncthreads();
    }
    if (threadIdx.x == 0) g_chunk[t][blockIdx.x] = red[0];
}

__global__ void select2_kernel() {
    __shared__ unsigned long long psum[1024];
    __shared__ int s_chunk;
    __shared__ unsigned long long s_intra;
    __shared__ float vs[2];
    int tid = threadIdx.x;
    for (int t = 0; t < 2; t++) {
        psum[tid] = g_chunk[t][tid];
        __syncthreads();
        for (int off = 1; off < 1024; off <<= 1) {
            unsigned long long v = 0;
            if (tid >= off) v = psum[tid - off];
            __syncthreads();
            psum[tid] += v;
            __syncthreads();
        }
        unsigned long long excl = tid ? psum[tid - 1] : 0ULL;
        unsigned long long R = g_irank[t];
        if (R >= excl && R < psum[tid]) { s_chunk = tid; s_intra = R - excl; }
        __syncthreads();
        int ck = s_chunk;
        unsigned long long Ri = s_intra;
        __syncthreads();
        psum[tid] = g_hist2[t][ck * 1024 + tid];
        __syncthreads();
        for (int off = 1; off < 1024; off <<= 1) {
            unsigned long long v = 0;
            if (tid >= off) v = psum[tid - off];
            __syncthreads();
            psum[tid] += v;
            __syncthreads();
        }
        unsigned long long excl2 = tid ? psum[tid - 1] : 0ULL;
        if (Ri >= excl2 && Ri < psum[tid])
            vs[t] = __uint_as_float((g_hibin[t] << 20) | (unsigned int)(ck * 1024 + tid));
        __syncthreads();
    }
    if (tid == 0) g_thr = vs[0] + 0.5f * (vs[1] - vs[0]);
}

// ============================================================
// Convert: fp32 -> fp16, PANEL layout with SW128 pre-swizzle.
// ============================================================
__global__ void conv_w_kernel(const float4* __restrict__ w) {
    float thr = g_thr;
    const int NU = NWELEM / 8;                   // 16B units
    int stride = gridDim.x * blockDim.x;
    char* dst = reinterpret_cast<char*>(g_wh);
    for (int u = blockIdx.x * blockDim.x + threadIdx.x; u < NU; u += stride) {
        float4 v0 = w[u * 2], v1 = w[u * 2 + 1];
        float f[8] = {v0.x, v0.y, v0.z, v0.w, v1.x, v1.y, v1.z, v1.w};
        uint4 o;
        unsigned int* op = reinterpret_cast<unsigned int*>(&o);
        #pragma unroll
        for (int j = 0; j < 4; j++) {
            float a = fabsf(f[2*j])   > thr ? f[2*j]   : 0.0f;
            float b = fabsf(f[2*j+1]) > thr ? f[2*j+1] : 0.0f;
            __half2 h = __floats2half2_rn(a, b);
            op[j] = *reinterpret_cast<unsigned int*>(&h);
        }
        int row = u >> 9;                         // 512 units per 4096-elem row
        int k8  = u & 511;
        int panel = k8 >> 3;
        unsigned int off = (row << 7) + ((k8 & 7) << 4);
        *reinterpret_cast<uint4*>(dst + (size_t)panel * PANEL_BYTES + SW128(off)) = o;
    }
}

__global__ void conv_x_kernel(const float4* __restrict__ x) {
    const int NU = (TOKENS * DIN) / 8;
    int stride = gridDim.x * blockDim.x;
    char* dst = reinterpret_cast<char*>(g_xh);
    for (int u = blockIdx.x * blockDim.x + threadIdx.x; u < NU; u += stride) {
        float4 v0 = x[u * 2], v1 = x[u * 2 + 1];
        float f[8] = {v0.x, v0.y, v0.z, v0.w, v1.x, v1.y, v1.z, v1.w};
        uint4 o;
        unsigned int* op = reinterpret_cast<unsigned int*>(&o);
        #pragma unroll
        for (int j = 0; j < 4; j++) {
            __half2 h = __floats2half2_rn(f[2*j], f[2*j+1]);
            op[j] = *reinterpret_cast<unsigned int*>(&h);
        }
        int row = u >> 9;
        int k8  = u & 511;
        int panel = k8 >> 3;
        unsigned int off = (row << 7) + ((k8 & 7) << 4);
        *reinterpret_cast<uint4*>(dst + (size_t)panel * PANEL_BYTES + SW128(off)) = o;
    }
}

// ============================================================
// GEMM: y = xh @ wh^T + bias.  Baseline tensor path (compute_103-safe):
// ldmatrix + mma.sync.m16n8k16 f16->f32.
// CTA tile 128(M) x 256(N), 8 compute warps (64x64 each) + 1 producer warp.
// K-chunk 64, 4-stage pipeline fed by cp.async.bulk (2 bulks/chunk).
// ============================================================
#define BM 128
#define BN 256
#define KC 64
#define STAGES 4
#define NKC (DIN / KC)                          // 64
#define A_BYTES (BM * 128)                      // 16384
#define B_BYTES (BN * 128)                      // 32768
#define STAGE_BYTES (A_BYTES + B_BYTES)         // 49152
#define A_OFF 0
#define B_OFF A_BYTES
#define SMEM_STAGE0 1024
#define SMEM_TOTAL (SMEM_STAGE0 + STAGES * STAGE_BYTES)  // 197632
#define NTHREADS 288                            // 8 compute warps + 1 producer warp

__global__ void __launch_bounds__(NTHREADS, 1)
gemm_kernel(const float* __restrict__ bias, float* __restrict__ y) {
    extern __shared__ __align__(1024) char smem[];
    uint32_t sbase = smem_u32(smem);
    int tid = threadIdx.x;
    int wid = tid >> 5;
    int lane = tid & 31;

    const int m0 = blockIdx.y * BM;
    const int n0 = blockIdx.x * BN;

    // barriers: full[s]@16+s*16 (expect_tx), empty[s]@24+s*16 (count 8)
    if (tid == 0) {
        #pragma unroll
        for (int s = 0; s < STAGES; s++) {
            MBAR_INIT(sbase + 16 + s * 16, 1);
            MBAR_INIT(sbase + 24 + s * 16, 8);
        }
    }
    __syncthreads();

    if (wid == 8) {
        // ---------- producer warp: single elected thread, 2 bulks / chunk ----
        if (elect_one()) {
            const char* Apan = reinterpret_cast<const char*>(g_xh) + (size_t)m0 * 128;
            const char* Bpan = reinterpret_cast<const char*>(g_wh) + (size_t)n0 * 128;
            int s = 0, pe = 1;
            for (int kc = 0; kc < NKC; kc++) {
                uint32_t stage = sbase + SMEM_STAGE0 + s * STAGE_BYTES;
                uint32_t fullb = sbase + 16 + s * 16;
                mbar_wait_rlx(sbase + 24 + s * 16, pe);   // post-wait = async proxy only
                MBAR_EXPECT_TX(fullb, STAGE_BYTES);
                bulk_g2s(stage + A_OFF, Apan + (size_t)kc * PANEL_BYTES, A_BYTES, fullb);
                bulk_g2s(stage + B_OFF, Bpan + (size_t)kc * PANEL_BYTES, B_BYTES, fullb);
                if (++s == STAGES) { s = 0; pe ^= 1; }
            }
        }
        return;
    }

    // ---------- compute warps 0-7: warp tile 64x64 ----------
    const int wm = (wid & 1) * 64;       // warp M offset (2 warps over 128)
    const int wn = (wid >> 1) * 64;      // warp N offset (4 warps over 256)

    // per-lane ldmatrix row addressing (unswizzled byte offsets; SW128 applied per use)
    // A .x4: matrices (m0-7,k0-7),(m8-15,k0-7),(m0-7,k8-15),(m8-15,k8-15)
    const uint32_t a_base = (uint32_t)((wm + (lane & 7) + ((lane >> 3) & 1) * 8) * 128
                                       + ((lane >> 4) & 1) * 16);
    // B^T .x4: matrices (n0-7,k0-7),(n0-7,k8-15),(n8-15,k0-7),(n8-15,k8-15)
    const uint32_t b_base = (uint32_t)((wn + (lane & 7) + ((lane >> 4) & 1) * 8) * 128
                                       + ((lane >> 3) & 1) * 16);

    float d[4][8][4];
    #pragma unroll
    for (int mt = 0; mt < 4; mt++)
        #pragma unroll
        for (int nt = 0; nt < 8; nt++)
            #pragma unroll
            for (int j = 0; j < 4; j++) d[mt][nt][j] = 0.0f;

    int s = 0, ph = 0;
    for (int kc = 0; kc < NKC; kc++) {
        uint32_t stage = sbase + SMEM_STAGE0 + s * STAGE_BYTES;
        mbar_wait_acq(sbase + 16 + s * 16, ph);
        uint32_t sA = stage + A_OFF, sB = stage + B_OFF;
        #pragma unroll
        for (int ks = 0; ks < 4; ks++) {          // 4 x k16 per 64-chunk
            uint32_t a[4][4], b[8][2];
            #pragma unroll
            for (int mt = 0; mt < 4; mt++) {
                uint32_t off = a_base + (uint32_t)(mt * 16 * 128 + ks * 32);
                ldmx4(a[mt][0], a[mt][1], a[mt][2], a[mt][3], sA + SW128(off));
            }
            #pragma unroll
            for (int p = 0; p < 4; p++) {         // n-tile pairs
                uint32_t off = b_base + (uint32_t)(p * 16 * 128 + ks * 32);
                uint32_t r0, r1, r2, r3;
                ldmx4(r0, r1, r2, r3, sB + SW128(off));
                b[p * 2][0] = r0; b[p * 2][1] = r1;
                b[p * 2 + 1][0] = r2; b[p * 2 + 1][1] = r3;
            }
            #pragma unroll
            for (int mt = 0; mt < 4; mt++)
                #pragma unroll
                for (int nt = 0; nt < 8; nt++)
                    mma16816(d[mt][nt], a[mt], b[nt]);
        }
        if (elect_one()) MBAR_ARRIVE(sbase + 24 + s * 16);
        if (++s == STAGES) { s = 0; ph ^= 1; }
    }

    // ---------- epilogue: regs + bias -> gmem (float2, full 32B sectors) ----
    const int g  = lane >> 2;
    const int tg = lane & 3;
    float2 bv[8];
    #pragma unroll
    for (int nt = 0; nt < 8; nt++)
        bv[nt] = *reinterpret_cast<const float2*>(bias + n0 + wn + nt * 8 + tg * 2);
    #pragma unroll
    for (int mt = 0; mt < 4; mt++) {
        #pragma unroll
        for (int h = 0; h < 2; h++) {
            int m = m0 + wm + mt * 16 + g + h * 8;
            float2* yrow = reinterpret_cast<float2*>(y + (size_t)m * DOUT);
            #pragma unroll
            for (int nt = 0; nt < 8; nt++) {
                float2 v;
                v.x = d[mt][nt][h * 2 + 0] + bv[nt].x;
                v.y = d[mt][nt][h * 2 + 1] + bv[nt].y;
                yrow[(n0 + wn + nt * 8 + tg * 2) >> 1] = v;
            }
        }
    }
}

// ============================================================
// kernel_launch
// ============================================================
extern "C" void kernel_launch(void* const* d_in, const int* in_sizes, int n_in,
                              void* d_out, int out_size) {
    const float* x    = (const float*)d_in[0];
    const float* w    = (const float*)d_in[1];
    const float* bias = (const float*)d_in[2];
    float* y          = (float*)d_out;

    void *ph1, *ph2;
    cudaGetSymbolAddress(&ph1, g_hist1);
    cudaGetSymbolAddress(&ph2, g_hist2);
    cudaMemsetAsync(ph1, 0, sizeof(g_hist1));
    cudaMemsetAsync(ph2, 0, sizeof(g_hist2));

    hist1_kernel<<<1024, 256>>>((const float4*)w);
    select1_kernel<<<1, 1024>>>();
    hist2_kernel<<<1024, 256>>>((const float4*)w);
    reduce2_kernel<<<dim3(1024, 2), 256>>>();
    select2_kernel<<<1, 1024>>>();

    conv_w_kernel<<<2048, 256>>>((const float4*)w);
    conv_x_kernel<<<2048, 256>>>((const float4*)x);

    cudaFuncSetAttribute(gemm_kernel, cudaFuncAttributeMaxDynamicSharedMemorySize, SMEM_TOTAL);
    dim3 grid(DOUT / BN, TOKENS / BM);  // (16, 32)
    gemm_kernel<<<grid, NTHREADS, SMEM_TOTAL>>>(bias, y);
}

// round 11
// speedup vs baseline: 1.0049x; 1.0049x over previous
#include <cuda_runtime.h>
#include <cuda_fp16.h>
#include <cstdint>
#include <cstddef>

// ============================================================
// Problem constants
// ============================================================
#define TOKENS 4096
#define DIN    4096
#define DOUT   4096
#define NWELEM (16777216)          // 4096*4096
// quantile(0.9) over n=16777216: index 0.9*(n-1)=15099493.5 -> ranks:
#define RANK0  15099493u
#define RANK1  15099494u

#define PANEL_BYTES ((size_t)TOKENS * 128)   // bytes per K-panel (both x and w): 512KB

// ============================================================
// Device scratch (static __device__ arrays: the sanctioned scratch)
// g_xh / g_wh hold fp16 data in PANEL layout, SW128 pre-swizzled:
//   element (row, k) lives at panel(k/64)*PANEL_BYTES + SW128(row*128 + (k%64)*2)
// ============================================================
__device__ __align__(1024) __half g_xh[(size_t)TOKENS * DIN];   // x in fp16, panelized
__device__ __align__(1024) __half g_wh[(size_t)DOUT * DIN];     // masked W fp16, panelized
__device__ unsigned int  g_hist1[4096];                // top-12-bit histogram
__device__ unsigned int  g_hist2[2][1 << 20];          // low-20-bit histograms (2 ranks)
__device__ unsigned int  g_chunk[2][1024];             // 1024-bin chunk sums of g_hist2
__device__ unsigned int  g_hibin[2];
__device__ unsigned int  g_irank[2];
__device__ unsigned int  g_count;                      // reduce2 completion counter
__device__ float         g_thr;

// ============================================================
// PTX helpers (baseline PTX only — compute_103-safe, no tcgen05)
// ============================================================
__device__ __forceinline__ uint32_t smem_u32(const void* p) {
    uint32_t a;
    asm("{ .reg .u64 t; cvta.to.shared.u64 t, %1; cvt.u32.u64 %0, t; }" : "=r"(a) : "l"(p));
    return a;
}

__device__ __forceinline__ uint32_t elect_one() {
    uint32_t pred;
    asm volatile("{\n\t.reg .pred p;\n\telect.sync _|p, 0xFFFFFFFF;\n\tselp.b32 %0, 1, 0, p;\n\t}"
                 : "=r"(pred));
    return pred;
}

#define MBAR_INIT(addr, cnt) \
    asm volatile("mbarrier.init.shared.b64 [%0], %1;" :: "r"(addr), "r"(cnt) : "memory")
#define MBAR_ARRIVE(addr) \
    asm volatile("mbarrier.arrive.shared.b64 _, [%0];" :: "r"(addr) : "memory")
#define MBAR_EXPECT_TX(addr, bytes) \
    asm volatile("mbarrier.arrive.expect_tx.shared.b64 _, [%0], %1;" :: "r"(addr), "r"(bytes) : "memory")

__device__ __forceinline__ void mbar_wait_acq(uint32_t addr, uint32_t parity) {
    asm volatile(
        "{\n\t.reg .pred P;\n\t"
        "WLA_%=:\n\t"
        "mbarrier.try_wait.parity.acquire.cta.shared::cta.b64 P, [%0], %1, 0x989680;\n\t"
        "@P bra.uni WDA_%=;\n\t"
        "bra.uni WLA_%=;\n\t"
        "WDA_%=:\n\t}"
        :: "r"(addr), "r"(parity) : "memory");
}
__device__ __forceinline__ void mbar_wait_rlx(uint32_t addr, uint32_t parity) {
    asm volatile(
        "{\n\t.reg .pred P;\n\t"
        "WLR_%=:\n\t"
        "mbarrier.try_wait.parity.relaxed.cta.shared::cta.b64 P, [%0], %1, 0x989680;\n\t"
        "@P bra.uni WDR_%=;\n\t"
        "bra.uni WLR_%=;\n\t"
        "WDR_%=:\n\t}"
        :: "r"(addr), "r"(parity) : "memory");
}

// Non-tensor bulk copy: contiguous GMEM -> SMEM, tx-count completion (UBLKCP).
__device__ __forceinline__ void bulk_g2s(uint32_t dst, const void* src,
                                         uint32_t bytes, uint32_t mbar) {
    asm volatile(
        "cp.async.bulk.shared::cluster.global.mbarrier::complete_tx::bytes [%0], [%1], %2, [%3];"
        :: "r"(dst), "l"(src), "r"(bytes), "r"(mbar) : "memory");
}

#define SW128(off) ((off) ^ (((off) >> 3) & 0x70))

// ldmatrix 4x 8x8 b16 matrices (baseline sm_75+)
__device__ __forceinline__ void ldmx4(uint32_t& r0, uint32_t& r1, uint32_t& r2, uint32_t& r3,
                                      uint32_t addr) {
    asm volatile("ldmatrix.sync.aligned.m8n8.x4.shared.b16 {%0,%1,%2,%3}, [%4];"
                 : "=r"(r0), "=r"(r1), "=r"(r2), "=r"(r3) : "r"(addr));
}

// mma.sync m16n8k16 fp16 in / fp32 accum (baseline sm_80+)
__device__ __forceinline__ void mma16816(float* d, const uint32_t* a, const uint32_t* b) {
    asm volatile(
        "mma.sync.aligned.m16n8k16.row.col.f32.f16.f16.f32 "
        "{%0,%1,%2,%3}, {%4,%5,%6,%7}, {%8,%9}, {%0,%1,%2,%3};"
        : "+f"(d[0]), "+f"(d[1]), "+f"(d[2]), "+f"(d[3])
        : "r"(a[0]), "r"(a[1]), "r"(a[2]), "r"(a[3]), "r"(b[0]), "r"(b[1]));
}

// ============================================================
// Launch 1: zero histograms + counter
// ============================================================
__global__ void zero_kernel() {
    const unsigned int total = 4096 + 2 * (1u << 20);   // u32 words
    unsigned int i = blockIdx.x * blockDim.x + threadIdx.x;
    unsigned int stride = gridDim.x * blockDim.x;
    for (unsigned int j = i; j < 4096; j += stride) g_hist1[j] = 0;
    unsigned int* h2 = &g_hist2[0][0];
    for (unsigned int j = i; j < total - 4096; j += stride) h2[j] = 0;
    if (i == 0) g_count = 0;
}

// ============================================================
// Launch 2: hist1 over |W| top-12 bits  +  conv_x (independent of thr)
// ============================================================
__global__ void hist1_convx_kernel(const float4* __restrict__ w, const float4* __restrict__ x) {
    __shared__ unsigned int h[4096];
    for (int i = threadIdx.x; i < 4096; i += blockDim.x) h[i] = 0;
    __syncthreads();
    int stride = gridDim.x * blockDim.x;
    int tid0 = blockIdx.x * blockDim.x + threadIdx.x;

    // conv_x: fp32 -> fp16 into pre-swizzled panel layout
    {
        const int NU = (TOKENS * DIN) / 8;
        char* dst = reinterpret_cast<char*>(g_xh);
        for (int u = tid0; u < NU; u += stride) {
            float4 v0 = x[u * 2], v1 = x[u * 2 + 1];
            float f[8] = {v0.x, v0.y, v0.z, v0.w, v1.x, v1.y, v1.z, v1.w};
            uint4 o;
            unsigned int* op = reinterpret_cast<unsigned int*>(&o);
            #pragma unroll
            for (int j = 0; j < 4; j++) {
                __half2 hh = __floats2half2_rn(f[2*j], f[2*j+1]);
                op[j] = *reinterpret_cast<unsigned int*>(&hh);
            }
            int row = u >> 9;
            int k8  = u & 511;
            int panel = k8 >> 3;
            unsigned int off = (row << 7) + ((k8 & 7) << 4);
            *reinterpret_cast<uint4*>(dst + (size_t)panel * PANEL_BYTES + SW128(off)) = o;
        }
    }

    // hist1 over W
    const int n4 = NWELEM / 4;
    for (int i = tid0; i < n4; i += stride) {
        float4 v = w[i];
        atomicAdd(&h[__float_as_uint(fabsf(v.x)) >> 20], 1u);
        atomicAdd(&h[__float_as_uint(fabsf(v.y)) >> 20], 1u);
        atomicAdd(&h[__float_as_uint(fabsf(v.z)) >> 20], 1u);
        atomicAdd(&h[__float_as_uint(fabsf(v.w)) >> 20], 1u);
    }
    __syncthreads();
    for (int i = threadIdx.x; i < 4096; i += blockDim.x)
        if (h[i]) atomicAdd(&g_hist1[i], h[i]);
}

// ============================================================
// Launch 3: select1 (per-CTA recompute from 4KB hist1) + hist2
// ============================================================
__global__ void hist2_sel1_kernel(const float4* __restrict__ w) {
    __shared__ unsigned int ps[256];
    __shared__ unsigned int sb[2];
    int tid = threadIdx.x;

    // ---- select1: each CTA recomputes hi-bins/intra-ranks (identical result) ----
    unsigned int c[16];
    unsigned int s = 0;
    #pragma unroll
    for (int j = 0; j < 16; j++) { c[j] = g_hist1[tid * 16 + j]; s += c[j]; }
    ps[tid] = s;
    __syncthreads();
    for (int off = 1; off < 256; off <<= 1) {
        unsigned int v = (tid >= off) ? ps[tid - off] : 0u;
        __syncthreads();
        ps[tid] += v;
        __syncthreads();
    }
    unsigned int excl = ps[tid] - s;
    const unsigned int R[2] = {RANK0, RANK1};
    #pragma unroll
    for (int t = 0; t < 2; t++) {
        if (R[t] >= excl && R[t] < excl + s) {
            unsigned int run = excl;
            #pragma unroll
            for (int j = 0; j < 16; j++) {
                if (R[t] < run + c[j]) {
                    sb[t] = tid * 16 + j;
                    g_hibin[t] = tid * 16 + j;     // duplicate identical writes: benign
                    g_irank[t] = R[t] - run;
                    break;
                }
                run += c[j];
            }
        }
    }
    __syncthreads();
    unsigned int b0 = sb[0], b1 = sb[1];
    bool dual = (b1 != b0);

    // ---- hist2: low-20-bit histogram of elements in the target hi-bin(s) ----
    const int n4 = NWELEM / 4;
    int stride = gridDim.x * blockDim.x;
    for (int i = blockIdx.x * blockDim.x + tid; i < n4; i += stride) {
        float4 v = w[i];
        float vv[4] = {v.x, v.y, v.z, v.w};
        #pragma unroll
        for (int j = 0; j < 4; j++) {
            unsigned int u = __float_as_uint(fabsf(vv[j]));
            unsigned int hi = u >> 20, lo = u & 0xFFFFFu;
            if (hi == b0) atomicAdd(&g_hist2[0][lo], 1u);
            if (dual && hi == b1) atomicAdd(&g_hist2[1][lo], 1u);
        }
    }
}

// ============================================================
// Launch 4: reduce hist2 to 1024 chunk sums; last-done block runs select2
// ============================================================
__global__ void reduce2_sel2_kernel() {
    int t = blockIdx.y;
    int base = blockIdx.x * 1024 + threadIdx.x * 4;
    const uint4* p = reinterpret_cast<const uint4*>(&g_hist2[t][base]);
    uint4 v = *p;
    unsigned int s = v.x + v.y + v.z + v.w;
    __shared__ unsigned int red[256];
    int tid = threadIdx.x;
    red[tid] = s;
    __syncthreads();
    for (int off = 128; off > 0; off >>= 1) {
        if (tid < off) red[tid] += red[tid + off];
        __syncthreads();
    }
    if (tid == 0) g_chunk[t][blockIdx.x] = red[0];

    // ---- completion detection ----
    __shared__ int lastf;
    if (tid == 0) {
        __threadfence();
        unsigned int done = atomicAdd(&g_count, 1u);
        lastf = (done == 2 * 1024 - 1);
    }
    __syncthreads();
    if (!lastf) return;

    // ---- select2 (256 threads): locate bin of each rank, set g_thr ----
    __shared__ unsigned int ps[256];
    __shared__ unsigned int s_ck, s_Ri;
    __shared__ float s_vs[2];
    unsigned int hb0 = g_hibin[0], hb1 = g_hibin[1];
    #pragma unroll
    for (int tt = 0; tt < 2; tt++) {
        int h = (tt == 1 && hb1 == hb0) ? 0 : tt;   // dual-bin aware
        unsigned int R = g_irank[tt];
        // level 1: find 1024-bin chunk
        unsigned int c4[4], cs = 0;
        #pragma unroll
        for (int j = 0; j < 4; j++) { c4[j] = g_chunk[h][tid * 4 + j]; cs += c4[j]; }
        ps[tid] = cs;
        __syncthreads();
        for (int off = 1; off < 256; off <<= 1) {
            unsigned int vv = (tid >= off) ? ps[tid - off] : 0u;
            __syncthreads();
            ps[tid] += vv;
            __syncthreads();
        }
        unsigned int excl = ps[tid] - cs;
        if (R >= excl && R < excl + cs) {
            unsigned int run = excl;
            #pragma unroll
            for (int j = 0; j < 4; j++) {
                if (R < run + c4[j]) { s_ck = tid * 4 + j; s_Ri = R - run; break; }
                run += c4[j];
            }
        }
        __syncthreads();
        unsigned int ck = s_ck, Ri = s_Ri;
        __syncthreads();
        // level 2: find bin within chunk
        unsigned int b4[4], bs = 0;
        #pragma unroll
        for (int j = 0; j < 4; j++) { b4[j] = g_hist2[h][ck * 1024 + tid * 4 + j]; bs += b4[j]; }
        ps[tid] = bs;
        __syncthreads();
        for (int off = 1; off < 256; off <<= 1) {
            unsigned int vv = (tid >= off) ? ps[tid - off] : 0u;
            __syncthreads();
            ps[tid] += vv;
            __syncthreads();
        }
        unsigned int excl2 = ps[tid] - bs;
        if (Ri >= excl2 && Ri < excl2 + bs) {
            unsigned int run = excl2;
            #pragma unroll
            for (int j = 0; j < 4; j++) {
                if (Ri < run + b4[j]) {
                    unsigned int binidx = ck * 1024 + tid * 4 + j;
                    s_vs[tt] = __uint_as_float((g_hibin[tt] << 20) | binidx);
                    break;
                }
                run += b4[j];
            }
        }
        __syncthreads();
    }
    if (tid == 0) g_thr = s_vs[0] + 0.5f * (s_vs[1] - s_vs[0]);
}

// ============================================================
// Launch 5: conv_w — mask strictly-above-thr, fp32 -> fp16, panelized
// ============================================================
__global__ void conv_w_kernel(const float4* __restrict__ w) {
    float thr = g_thr;
    const int NU = NWELEM / 8;                   // 16B units
    int stride = gridDim.x * blockDim.x;
    char* dst = reinterpret_cast<char*>(g_wh);
    for (int u = blockIdx.x * blockDim.x + threadIdx.x; u < NU; u += stride) {
        float4 v0 = w[u * 2], v1 = w[u * 2 + 1];
        float f[8] = {v0.x, v0.y, v0.z, v0.w, v1.x, v1.y, v1.z, v1.w};
        uint4 o;
        unsigned int* op = reinterpret_cast<unsigned int*>(&o);
        #pragma unroll
        for (int j = 0; j < 4; j++) {
            float a = fabsf(f[2*j])   > thr ? f[2*j]   : 0.0f;
            float b = fabsf(f[2*j+1]) > thr ? f[2*j+1] : 0.0f;
            __half2 h = __floats2half2_rn(a, b);
            op[j] = *reinterpret_cast<unsigned int*>(&h);
        }
        int row = u >> 9;                         // 512 units per 4096-elem row
        int k8  = u & 511;
        int panel = k8 >> 3;
        unsigned int off = (row << 7) + ((k8 & 7) << 4);
        *reinterpret_cast<uint4*>(dst + (size_t)panel * PANEL_BYTES + SW128(off)) = o;
    }
}

// ============================================================
// Launch 6: GEMM y = xh @ wh^T + bias (unchanged from passing R9 kernel)
// ldmatrix + mma.sync.m16n8k16 f16->f32.
// CTA tile 128(M) x 256(N), 8 compute warps (64x64 each) + 1 producer warp.
// K-chunk 64, 4-stage pipeline fed by cp.async.bulk (2 bulks/chunk).
// ============================================================
#define BM 128
#define BN 256
#define KC 64
#define STAGES 4
#define NKC (DIN / KC)                          // 64
#define A_BYTES (BM * 128)                      // 16384
#define B_BYTES (BN * 128)                      // 32768
#define STAGE_BYTES (A_BYTES + B_BYTES)         // 49152
#define A_OFF 0
#define B_OFF A_BYTES
#define SMEM_STAGE0 1024
#define SMEM_TOTAL (SMEM_STAGE0 + STAGES * STAGE_BYTES)  // 197632
#define NTHREADS 288                            // 8 compute warps + 1 producer warp

__global__ void __launch_bounds__(NTHREADS, 1)
gemm_kernel(const float* __restrict__ bias, float* __restrict__ y) {
    extern __shared__ __align__(1024) char smem[];
    uint32_t sbase = smem_u32(smem);
    int tid = threadIdx.x;
    int wid = tid >> 5;
    int lane = tid & 31;

    const int m0 = blockIdx.y * BM;
    const int n0 = blockIdx.x * BN;

    // barriers: full[s]@16+s*16 (expect_tx), empty[s]@24+s*16 (count 8)
    if (tid == 0) {
        #pragma unroll
        for (int s = 0; s < STAGES; s++) {
            MBAR_INIT(sbase + 16 + s * 16, 1);
            MBAR_INIT(sbase + 24 + s * 16, 8);
        }
    }
    __syncthreads();

    if (wid == 8) {
        // ---------- producer warp: single elected thread, 2 bulks / chunk ----
        if (elect_one()) {
            const char* Apan = reinterpret_cast<const char*>(g_xh) + (size_t)m0 * 128;
            const char* Bpan = reinterpret_cast<const char*>(g_wh) + (size_t)n0 * 128;
            int s = 0, pe = 1;
            for (int kc = 0; kc < NKC; kc++) {
                uint32_t stage = sbase + SMEM_STAGE0 + s * STAGE_BYTES;
                uint32_t fullb = sbase + 16 + s * 16;
                mbar_wait_rlx(sbase + 24 + s * 16, pe);   // post-wait = async proxy only
                MBAR_EXPECT_TX(fullb, STAGE_BYTES);
                bulk_g2s(stage + A_OFF, Apan + (size_t)kc * PANEL_BYTES, A_BYTES, fullb);
                bulk_g2s(stage + B_OFF, Bpan + (size_t)kc * PANEL_BYTES, B_BYTES, fullb);
                if (++s == STAGES) { s = 0; pe ^= 1; }
            }
        }
        return;
    }

    // ---------- compute warps 0-7: warp tile 64x64 ----------
    const int wm = (wid & 1) * 64;       // warp M offset (2 warps over 128)
    const int wn = (wid >> 1) * 64;      // warp N offset (4 warps over 256)

    // per-lane ldmatrix row addressing (unswizzled byte offsets; SW128 applied per use)
    // A .x4: matrices (m0-7,k0-7),(m8-15,k0-7),(m0-7,k8-15),(m8-15,k8-15)
    const uint32_t a_base = (uint32_t)((wm + (lane & 7) + ((lane >> 3) & 1) * 8) * 128
                                       + ((lane >> 4) & 1) * 16);
    // B^T .x4: matrices (n0-7,k0-7),(n0-7,k8-15),(n8-15,k0-7),(n8-15,k8-15)
    const uint32_t b_base = (uint32_t)((wn + (lane & 7) + ((lane >> 4) & 1) * 8) * 128
                                       + ((lane >> 3) & 1) * 16);

    float d[4][8][4];
    #pragma unroll
    for (int mt = 0; mt < 4; mt++)
        #pragma unroll
        for (int nt = 0; nt < 8; nt++)
            #pragma unroll
            for (int j = 0; j < 4; j++) d[mt][nt][j] = 0.0f;

    int s = 0, ph = 0;
    for (int kc = 0; kc < NKC; kc++) {
        uint32_t stage = sbase + SMEM_STAGE0 + s * STAGE_BYTES;
        mbar_wait_acq(sbase + 16 + s * 16, ph);
        uint32_t sA = stage + A_OFF, sB = stage + B_OFF;
        #pragma unroll
        for (int ks = 0; ks < 4; ks++) {          // 4 x k16 per 64-chunk
            uint32_t a[4][4], b[8][2];
            #pragma unroll
            for (int mt = 0; mt < 4; mt++) {
                uint32_t off = a_base + (uint32_t)(mt * 16 * 128 + ks * 32);
                ldmx4(a[mt][0], a[mt][1], a[mt][2], a[mt][3], sA + SW128(off));
            }
            #pragma unroll
            for (int p = 0; p < 4; p++) {         // n-tile pairs
                uint32_t off = b_base + (uint32_t)(p * 16 * 128 + ks * 32);
                uint32_t r0, r1, r2, r3;
                ldmx4(r0, r1, r2, r3, sB + SW128(off));
                b[p * 2][0] = r0; b[p * 2][1] = r1;
                b[p * 2 + 1][0] = r2; b[p * 2 + 1][1] = r3;
            }
            #pragma unroll
            for (int mt = 0; mt < 4; mt++)
                #pragma unroll
                for (int nt = 0; nt < 8; nt++)
                    mma16816(d[mt][nt], a[mt], b[nt]);
        }
        if (elect_one()) MBAR_ARRIVE(sbase + 24 + s * 16);
        if (++s == STAGES) { s = 0; ph ^= 1; }
    }

    // ---------- epilogue: regs + bias -> gmem (float2, full 32B sectors) ----
    const int g  = lane >> 2;
    const int tg = lane & 3;
    float2 bv[8];
    #pragma unroll
    for (int nt = 0; nt < 8; nt++)
        bv[nt] = *reinterpret_cast<const float2*>(bias + n0 + wn + nt * 8 + tg * 2);
    #pragma unroll
    for (int mt = 0; mt < 4; mt++) {
        #pragma unroll
        for (int h = 0; h < 2; h++) {
            int m = m0 + wm + mt * 16 + g + h * 8;
            float2* yrow = reinterpret_cast<float2*>(y + (size_t)m * DOUT);
            #pragma unroll
            for (int nt = 0; nt < 8; nt++) {
                float2 v;
                v.x = d[mt][nt][h * 2 + 0] + bv[nt].x;
                v.y = d[mt][nt][h * 2 + 1] + bv[nt].y;
                yrow[(n0 + wn + nt * 8 + tg * 2) >> 1] = v;
            }
        }
    }
}

// ============================================================
// kernel_launch — 6 launches; GEMM is launch #6 (ncu -s 5 captures it)
// ============================================================
extern "C" void kernel_launch(void* const* d_in, const int* in_sizes, int n_in,
                              void* d_out, int out_size) {
    const float* x    = (const float*)d_in[0];
    const float* w    = (const float*)d_in[1];
    const float* bias = (const float*)d_in[2];
    float* y          = (float*)d_out;

    zero_kernel<<<2048, 256>>>();
    hist1_convx_kernel<<<2048, 256>>>((const float4*)w, (const float4*)x);
    hist2_sel1_kernel<<<1024, 256>>>((const float4*)w);
    reduce2_sel2_kernel<<<dim3(1024, 2), 256>>>();
    conv_w_kernel<<<2048, 256>>>((const float4*)w);

    cudaFuncSetAttribute(gemm_kernel, cudaFuncAttributeMaxDynamicSharedMemorySize, SMEM_TOTAL);
    dim3 grid(DOUT / BN, TOKENS / BM);  // (16, 32)
    gemm_kernel<<<grid, NTHREADS, SMEM_TOTAL>>>(bias, y);
}